// round 1
// baseline (speedup 1.0000x reference)
#include <cuda_runtime.h>
#include <math.h>

#define TWO_PI_F 6.283185307179586f

// Output 1: weight_H_out [512, 16, 512, 16] = 67,108,864 floats
// Output 2: w            [512, 16, 7, 7]    =    401,408 floats
#define OUT1_ELEMS 67108864
#define O_DIM   512
#define CIN_DIM 512
#define K_DIM   16
#define NI_DIM  16
#define NO_DIM  16
#define KS_DIM  7

// ---------------------------------------------------------------------------
// Kernel 1: weight_H_out[o, ni, c, no] =
//   (1-frac[ni,no]) * weight_H[o,c,i0[ni,no]] + frac[ni,no] * weight_H[o,c,i1]
// One thread per (o, c). Row of 16 weights loaded once, parked in padded smem
// (dynamic i0 index, conflict-free at stride 17). 256 outputs per thread,
// written as 4 x float4 per ni.
// ---------------------------------------------------------------------------
__global__ __launch_bounds__(256) void gsep_lerp_kernel(
    const float* __restrict__ in_H,
    const float* __restrict__ out_H,
    const float* __restrict__ weight_H,
    float* __restrict__ out)
{
    __shared__ float sfrac[NI_DIM * NO_DIM];
    __shared__ int   sidx [NI_DIM * NO_DIM];
    __shared__ float srow [256 * 17];

    const int t = threadIdx.x;

    // --- precompute (i0, frac) for all 256 (ni, no) pairs: one per thread ---
    {
        const int ni = t >> 4;
        const int no = t & 15;
        float d = in_H[ni] - out_H[no];       // in (-2pi, 2pi)
        float r = fmodf(d, TWO_PI_F);
        if (r < 0.0f) r += TWO_PI_F;          // python-mod semantics, in [0, 2pi]
        float tt = r * (16.0f / TWO_PI_F);    // in [0, 16]
        float fl = floorf(tt);
        sidx[t]  = ((int)fl) & 15;            // matches reference's % K (handles tt==16 edge)
        sfrac[t] = tt - fl;
    }

    // --- load this thread's weight row (o,c) into padded shared ---
    const int gid = blockIdx.x * 256 + t;     // gid = o*512 + c
    const float4* wr = (const float4*)(weight_H + (size_t)gid * 16);
    float4 w0 = wr[0], w1 = wr[1], w2 = wr[2], w3 = wr[3];
    float* myrow = srow + t * 17;
    myrow[0]  = w0.x; myrow[1]  = w0.y; myrow[2]  = w0.z; myrow[3]  = w0.w;
    myrow[4]  = w1.x; myrow[5]  = w1.y; myrow[6]  = w1.z; myrow[7]  = w1.w;
    myrow[8]  = w2.x; myrow[9]  = w2.y; myrow[10] = w2.z; myrow[11] = w2.w;
    myrow[12] = w3.x; myrow[13] = w3.y; myrow[14] = w3.z; myrow[15] = w3.w;

    __syncthreads();

    const int o = gid >> 9;
    const int c = gid & 511;

    #pragma unroll 1
    for (int ni = 0; ni < NI_DIM; ni++) {
        float res[16];
        #pragma unroll
        for (int q = 0; q < 16; q++) {
            const int e  = ni * 16 + q;       // uniform across warp -> LDS broadcast
            const int i0 = sidx[e];
            const float f = sfrac[e];
            const float a = myrow[i0];
            const float b = myrow[(i0 + 1) & 15];
            res[q] = fmaf(f, b - a, a);       // (1-f)*a + f*b
        }
        float4* obase = (float4*)(out + ((((size_t)o * 16 + ni) * 512 + c) << 4));
        obase[0] = make_float4(res[0],  res[1],  res[2],  res[3]);
        obase[1] = make_float4(res[4],  res[5],  res[6],  res[7]);
        obase[2] = make_float4(res[8],  res[9],  res[10], res[11]);
        obase[3] = make_float4(res[12], res[13], res[14], res[15]);
    }
}

// ---------------------------------------------------------------------------
// Kernel 2: w[o, no, ky, kx] = mask[ky,kx] * bilinear(weight[o], R(-out_H[no]) @ grid)
// One thread per output element (401,408 total). Tiny; ALU-trivial.
// ---------------------------------------------------------------------------
__global__ void gsep_rot_kernel(
    const float* __restrict__ out_H,
    const float* __restrict__ weight,     // [512, 1, 7, 7]
    const float* __restrict__ grid_Rn,    // [7, 7, 2]
    const float* __restrict__ mask,       // [7, 7]
    float* __restrict__ out2)
{
    const int idx = blockIdx.x * blockDim.x + threadIdx.x;
    const int total = O_DIM * NO_DIM * KS_DIM * KS_DIM;
    if (idx >= total) return;

    const int pix = idx % (KS_DIM * KS_DIM);
    const int on  = idx / (KS_DIM * KS_DIM);
    const int no  = on & 15;
    const int o   = on >> 4;

    const float gx = grid_Rn[pix * 2 + 0];
    const float gy = grid_Rn[pix * 2 + 1];

    const float ang = -out_H[no];
    float sn, cs;
    sincosf(ang, &sn, &cs);
    // R = [[c, -s], [s, c]] applied to (gx, gy)
    const float xr = cs * gx - sn * gy;
    const float yr = sn * gx + cs * gy;

    // align_corners map to [0, KS-1]
    const float x = (xr + 1.0f) * 0.5f * (float)(KS_DIM - 1);
    const float y = (yr + 1.0f) * 0.5f * (float)(KS_DIM - 1);
    const float x0f = floorf(x), y0f = floorf(y);
    const float wx = x - x0f,    wy = y - y0f;
    const int x0 = (int)x0f,     y0 = (int)y0f;

    const float* img = weight + o * (KS_DIM * KS_DIM);

    auto g = [&](int yy, int xx) -> float {
        if (yy < 0 || yy >= KS_DIM || xx < 0 || xx >= KS_DIM) return 0.0f;
        return img[yy * KS_DIM + xx];
    };

    const float v = (1.0f - wy) * (1.0f - wx) * g(y0,     x0)
                  + (1.0f - wy) * wx          * g(y0,     x0 + 1)
                  + wy          * (1.0f - wx) * g(y0 + 1, x0)
                  + wy          * wx          * g(y0 + 1, x0 + 1);

    out2[idx] = mask[pix] * v;
}

// ---------------------------------------------------------------------------
extern "C" void kernel_launch(void* const* d_in, const int* in_sizes, int n_in,
                              void* d_out, int out_size)
{
    const float* in_H     = (const float*)d_in[0];  // [16, 1]
    const float* out_H    = (const float*)d_in[1];  // [16, 1]
    const float* weight_H = (const float*)d_in[2];  // [512, 512, 16]
    const float* weight   = (const float*)d_in[3];  // [512, 1, 7, 7]
    // d_in[4] = grid_H (implicit uniform grid; unused)
    const float* grid_Rn  = (const float*)d_in[5];  // [7, 7, 2]
    const float* mask     = (const float*)d_in[6];  // [7, 7]

    float* out = (float*)d_out;

    // Kernel 1: 512*512 threads, one per (o, c)
    gsep_lerp_kernel<<<(O_DIM * CIN_DIM) / 256, 256>>>(in_H, out_H, weight_H, out);

    // Kernel 2: one thread per element of out2
    const int total2 = O_DIM * NO_DIM * KS_DIM * KS_DIM;
    gsep_rot_kernel<<<(total2 + 255) / 256, 256>>>(out_H, weight, grid_Rn, mask,
                                                   out + OUT1_ELEMS);
}

// round 2
// speedup vs baseline: 1.3379x; 1.3379x over previous
#include <cuda_runtime.h>
#include <math.h>

#define TWO_PI_F 6.283185307179586f

// Output 1: weight_H_out [512, 16, 512, 16] = 67,108,864 floats
// Output 2: w            [512, 16, 7, 7]    =    401,408 floats
#define OUT1_ELEMS 67108864
#define O_DIM   512
#define CIN_DIM 512
#define K_DIM   16
#define NI_DIM  16
#define NO_DIM  16
#define KS_DIM  7

#define LERP_BLOCKS (O_DIM * (CIN_DIM / 64))          // 4096: (o, c_block of 64)
#define ROT_TOTAL   (O_DIM * NO_DIM * KS_DIM * KS_DIM) // 401408
#define ROT_BLOCKS  ((ROT_TOTAL + 255) / 256)          // 1568

// ---------------------------------------------------------------------------
// Fused kernel.
//  Blocks [0, LERP_BLOCKS): weight_H_out.
//    block -> o = b>>3, c_base = (b&7)*64.
//    smem holds 64 weight rows (stride-17 padded) loaded with ONE coalesced
//    read; each row hits DRAM exactly once.
//    thread -> c_local = t>>2, no_quad = t&3. Loops ni=0..15, writes one
//    float4 per iter; warp writes 512B fully contiguous (4 full 128B lines).
//  Blocks [LERP_BLOCKS, +ROT_BLOCKS): rotated bilinear resample (tiny).
// ---------------------------------------------------------------------------
__global__ __launch_bounds__(256) void gsep_fused_kernel(
    const float* __restrict__ in_H,
    const float* __restrict__ out_H,
    const float* __restrict__ weight_H,   // [512, 512, 16]
    const float* __restrict__ weight,     // [512, 1, 7, 7]
    const float* __restrict__ grid_Rn,    // [7, 7, 2]
    const float* __restrict__ mask,       // [7, 7]
    float* __restrict__ out)              // out1 | out2
{
    const int b = blockIdx.x;
    const int t = threadIdx.x;

    if (b < LERP_BLOCKS) {
        __shared__ float sfrac[NI_DIM * NO_DIM];
        __shared__ int   sidx [NI_DIM * NO_DIM];
        __shared__ float srow [64 * 17];

        // --- (i0, frac) for all 256 (ni, no) pairs: one per thread ---
        {
            const int ni = t >> 4;
            const int no = t & 15;
            float d = in_H[ni] - out_H[no];
            float r = fmodf(d, TWO_PI_F);
            if (r < 0.0f) r += TWO_PI_F;          // floor-mod, [0, 2pi]
            float tt = r * (16.0f / TWO_PI_F);    // [0, 16]
            float fl = floorf(tt);
            sidx[t]  = ((int)fl) & 15;            // matches reference % K
            sfrac[t] = tt - fl;
        }

        // --- cooperative load: 64 rows x 16 floats, coalesced float4 reads ---
        const int o      = b >> 3;
        const int c_base = (b & 7) * 64;
        {
            const float4 v = ((const float4*)(weight_H
                              + ((size_t)o * 512 + c_base) * 16))[t];
            const int r   = t >> 2;          // row 0..63
            const int col = (t & 3) * 4;     // 0,4,8,12
            float* dst = srow + r * 17 + col;
            dst[0] = v.x; dst[1] = v.y; dst[2] = v.z; dst[3] = v.w;
        }
        __syncthreads();

        const int c_local = t >> 2;          // 0..63
        const int noq     = t & 3;           // which no-quad
        const float* row  = srow + c_local * 17;

        #pragma unroll 1
        for (int ni = 0; ni < NI_DIM; ni++) {
            const int e = ni * 16 + noq * 4;
            float res[4];
            #pragma unroll
            for (int j = 0; j < 4; j++) {
                const int   i0 = sidx[e + j];
                const float f  = sfrac[e + j];
                const float a  = row[i0];
                const float bb = row[(i0 + 1) & 15];
                res[j] = fmaf(f, bb - a, a);
            }
            float4 v4 = make_float4(res[0], res[1], res[2], res[3]);
            float* dst = out + ((((size_t)o * 16 + ni) * 512 + c_base + c_local) << 4)
                             + noq * 4;
            __stcs((float4*)dst, v4);        // streaming store: don't pollute L2
        }
        return;
    }

    // -------------------- rotated bilinear resample part --------------------
    const int idx = (b - LERP_BLOCKS) * 256 + t;
    if (idx >= ROT_TOTAL) return;

    const int pix = idx % (KS_DIM * KS_DIM);
    const int on  = idx / (KS_DIM * KS_DIM);
    const int no  = on & 15;
    const int o   = on >> 4;

    const float gx = grid_Rn[pix * 2 + 0];
    const float gy = grid_Rn[pix * 2 + 1];

    const float ang = -out_H[no];
    float sn, cs;
    sincosf(ang, &sn, &cs);
    const float xr = cs * gx - sn * gy;
    const float yr = sn * gx + cs * gy;

    const float x = (xr + 1.0f) * 0.5f * (float)(KS_DIM - 1);
    const float y = (yr + 1.0f) * 0.5f * (float)(KS_DIM - 1);
    const float x0f = floorf(x), y0f = floorf(y);
    const float wx = x - x0f,    wy = y - y0f;
    const int x0 = (int)x0f,     y0 = (int)y0f;

    const float* img = weight + o * (KS_DIM * KS_DIM);

    auto g = [&](int yy, int xx) -> float {
        if (yy < 0 || yy >= KS_DIM || xx < 0 || xx >= KS_DIM) return 0.0f;
        return img[yy * KS_DIM + xx];
    };

    const float v = (1.0f - wy) * (1.0f - wx) * g(y0,     x0)
                  + (1.0f - wy) * wx          * g(y0,     x0 + 1)
                  + wy          * (1.0f - wx) * g(y0 + 1, x0)
                  + wy          * wx          * g(y0 + 1, x0 + 1);

    out[OUT1_ELEMS + idx] = mask[pix] * v;
}

// ---------------------------------------------------------------------------
extern "C" void kernel_launch(void* const* d_in, const int* in_sizes, int n_in,
                              void* d_out, int out_size)
{
    const float* in_H     = (const float*)d_in[0];  // [16, 1]
    const float* out_H    = (const float*)d_in[1];  // [16, 1]
    const float* weight_H = (const float*)d_in[2];  // [512, 512, 16]
    const float* weight   = (const float*)d_in[3];  // [512, 1, 7, 7]
    // d_in[4] = grid_H (uniform grid, implicit; unused)
    const float* grid_Rn  = (const float*)d_in[5];  // [7, 7, 2]
    const float* mask     = (const float*)d_in[6];  // [7, 7]

    gsep_fused_kernel<<<LERP_BLOCKS + ROT_BLOCKS, 256>>>(
        in_H, out_H, weight_H, weight, grid_Rn, mask, (float*)d_out);
}

// round 3
// speedup vs baseline: 1.5921x; 1.1900x over previous
#include <cuda_runtime.h>
#include <math.h>

#define TWO_PI_F 6.283185307179586f

#define OUT1_ELEMS 67108864
#define O_DIM   512
#define CIN_DIM 512
#define K_DIM   16
#define NI_DIM  16
#define NO_DIM  16
#define KS_DIM  7

#define LERP_BLOCKS (O_DIM * (CIN_DIM / 64))           // 4096: (o, c_block of 64)
#define ROT_TOTAL   (O_DIM * NO_DIM * KS_DIM * KS_DIM) // 401408
#define ROT_BLOCKS  ((ROT_TOTAL + 255) / 256)          // 1568

#define PAIR_STRIDE 17   // float2 units per row (17*8 = 136B, 8B aligned)

// ---------------------------------------------------------------------------
// Fused kernel.
//  Blocks [0, LERP_BLOCKS): weight_H_out [o, ni, c, no].
//    block: o = b>>3, c_base = (b&7)*64. smem: pair[c][k] = (W[k], W[k+1 mod 16])
//    as float2 -> one LDS.64 per lerp. (i0, frac) live in registers: warp w
//    owns ni in {2w, 2w+1}; lane = c_idx*4 + noq; thread precomputes its
//    8 (i0, f) pairs once. Inner loop: 4x LDS.64 + 4 FMA + 1 STG.128 (stcs).
//  Blocks [LERP_BLOCKS, ...): rotated bilinear resample (tiny).
// ---------------------------------------------------------------------------
__global__ __launch_bounds__(256) void gsep_fused_kernel(
    const float* __restrict__ in_H,
    const float* __restrict__ out_H,
    const float* __restrict__ weight_H,   // [512, 512, 16]
    const float* __restrict__ weight,     // [512, 1, 7, 7]
    const float* __restrict__ grid_Rn,    // [7, 7, 2]
    const float* __restrict__ mask,       // [7, 7]
    float* __restrict__ out)              // out1 | out2
{
    const int b = blockIdx.x;
    const int t = threadIdx.x;

    if (b < LERP_BLOCKS) {
        __shared__ float2 pairs[64 * PAIR_STRIDE];

        const int o      = b >> 3;
        const int c_base = (b & 7) * 64;
        const int lane   = t & 31;
        const int warp   = t >> 5;        // 0..7
        const int noq    = lane & 3;      // quad of no
        const int c_idx  = lane >> 2;     // 0..7 within a c-chunk

        // --- build overlapped-pair table from one coalesced float4 read ---
        {
            const float4 v = ((const float4*)(weight_H
                              + ((size_t)o * 512 + c_base) * 16))[t];
            const int r = t >> 2;          // smem row 0..63
            const int q = t & 3;           // which float4 of the row
            // neighbor value: row[col+4] (next thread's v.x) or row[0] (q==3 wrap)
            float down_x = __shfl_down_sync(0xffffffffu, v.x, 1);
            float base_x = __shfl_sync(0xffffffffu, v.x, lane & ~3);
            float nxt = (q == 3) ? base_x : down_x;
            float2* prow = pairs + r * PAIR_STRIDE + q * 4;
            prow[0] = make_float2(v.x, v.y);
            prow[1] = make_float2(v.y, v.z);
            prow[2] = make_float2(v.z, v.w);
            prow[3] = make_float2(v.w, nxt);
        }

        // --- per-thread (i0, frac): 2 ni x 4 no, all in registers ---
        int   i0r[2][4];
        float frr[2][4];
        #pragma unroll
        for (int n2 = 0; n2 < 2; n2++) {
            const int ni = warp * 2 + n2;
            const float ih = __ldg(in_H + ni);
            #pragma unroll
            for (int j = 0; j < 4; j++) {
                const int no = noq * 4 + j;
                float d = ih - __ldg(out_H + no);
                float r = fmodf(d, TWO_PI_F);
                if (r < 0.0f) r += TWO_PI_F;
                float tt = r * (16.0f / TWO_PI_F);
                float fl = floorf(tt);
                i0r[n2][j] = ((int)fl) & 15;
                frr[n2][j] = tt - fl;
            }
        }

        __syncthreads();

        #pragma unroll
        for (int n2 = 0; n2 < 2; n2++) {
            const int ni = warp * 2 + n2;
            float* obase = out + ((((size_t)o * 16 + ni) * 512 + c_base) << 4)
                               + noq * 4;
            #pragma unroll 1
            for (int chunk = 0; chunk < 8; chunk++) {
                const int c_local = chunk * 8 + c_idx;
                const float2* prow = pairs + c_local * PAIR_STRIDE;
                float res[4];
                #pragma unroll
                for (int j = 0; j < 4; j++) {
                    const float2 ab = prow[i0r[n2][j]];
                    res[j] = fmaf(frr[n2][j], ab.y - ab.x, ab.x);
                }
                __stcs((float4*)(obase + (size_t)c_local * 16),
                       make_float4(res[0], res[1], res[2], res[3]));
            }
        }
        return;
    }

    // -------------------- rotated bilinear resample part --------------------
    const int idx = (b - LERP_BLOCKS) * 256 + t;
    if (idx >= ROT_TOTAL) return;

    const int pix = idx % (KS_DIM * KS_DIM);
    const int on  = idx / (KS_DIM * KS_DIM);
    const int no  = on & 15;
    const int o   = on >> 4;

    const float gx = grid_Rn[pix * 2 + 0];
    const float gy = grid_Rn[pix * 2 + 1];

    const float ang = -out_H[no];
    float sn, cs;
    sincosf(ang, &sn, &cs);
    const float xr = cs * gx - sn * gy;
    const float yr = sn * gx + cs * gy;

    const float x = (xr + 1.0f) * 0.5f * (float)(KS_DIM - 1);
    const float y = (yr + 1.0f) * 0.5f * (float)(KS_DIM - 1);
    const float x0f = floorf(x), y0f = floorf(y);
    const float wx = x - x0f,    wy = y - y0f;
    const int x0 = (int)x0f,     y0 = (int)y0f;

    const float* img = weight + o * (KS_DIM * KS_DIM);

    auto g = [&](int yy, int xx) -> float {
        if (yy < 0 || yy >= KS_DIM || xx < 0 || xx >= KS_DIM) return 0.0f;
        return img[yy * KS_DIM + xx];
    };

    const float v = (1.0f - wy) * (1.0f - wx) * g(y0,     x0)
                  + (1.0f - wy) * wx          * g(y0,     x0 + 1)
                  + wy          * (1.0f - wx) * g(y0 + 1, x0)
                  + wy          * wx          * g(y0 + 1, x0 + 1);

    out[OUT1_ELEMS + idx] = mask[pix] * v;
}

// ---------------------------------------------------------------------------
extern "C" void kernel_launch(void* const* d_in, const int* in_sizes, int n_in,
                              void* d_out, int out_size)
{
    const float* in_H     = (const float*)d_in[0];  // [16, 1]
    const float* out_H    = (const float*)d_in[1];  // [16, 1]
    const float* weight_H = (const float*)d_in[2];  // [512, 512, 16]
    const float* weight   = (const float*)d_in[3];  // [512, 1, 7, 7]
    // d_in[4] = grid_H (uniform grid, implicit; unused)
    const float* grid_Rn  = (const float*)d_in[5];  // [7, 7, 2]
    const float* mask     = (const float*)d_in[6];  // [7, 7]

    gsep_fused_kernel<<<LERP_BLOCKS + ROT_BLOCKS, 256>>>(
        in_H, out_H, weight_H, weight, grid_Rn, mask, (float*)d_out);
}

// round 4
// speedup vs baseline: 1.8614x; 1.1692x over previous
#include <cuda_runtime.h>
#include <math.h>

#define TWO_PI_F 6.283185307179586f

#define OUT1_ELEMS 67108864
#define O_DIM   512
#define CIN_DIM 512
#define K_DIM   16
#define NI_DIM  16
#define NO_DIM  16
#define KS_DIM  7

#define LERP_BLOCKS (O_DIM * (CIN_DIM / 64))           // 4096: (o, c_block of 64)
#define ROT_TOTAL   (O_DIM * NO_DIM * KS_DIM * KS_DIM) // 401408
#define ROT_BLOCKS  ((ROT_TOTAL + 255) / 256)          // 1568

#define TP2_STRIDE 33   // float4 units per k-row (33*16B; (i0+cc)%8 spreads all bank-quads)

// ---------------------------------------------------------------------------
// Fused kernel.
//  Blocks [0, LERP_BLOCKS): weight_H_out [o, ni, c, no].
//   smem table tp2[k][cc] = (W[cc][k], W[cc][k+1], W[cc+32][k], W[cc+32][k+1])
//   -> one LDS.128 yields lerp endpoints for TWO c values. Bank-quad slot is
//   (k + cc) mod 8, so each noq-group sweeps all 8 quads: exactly 4 wavefronts
//   per LDS.128, independent of runtime i0 values. (i0, frac) in registers.
//   Hot loop per warp-iter: 4 LDS.128 + 8 FMA + 2 STG.128 (contiguous 512B).
//  Blocks [LERP_BLOCKS, ...): rotated bilinear resample (tiny).
// ---------------------------------------------------------------------------
__global__ __launch_bounds__(256) void gsep_fused_kernel(
    const float* __restrict__ in_H,
    const float* __restrict__ out_H,
    const float* __restrict__ weight_H,   // [512, 512, 16]
    const float* __restrict__ weight,     // [512, 1, 7, 7]
    const float* __restrict__ grid_Rn,    // [7, 7, 2]
    const float* __restrict__ mask,       // [7, 7]
    float* __restrict__ out)              // out1 | out2
{
    const int b = blockIdx.x;
    const int t = threadIdx.x;

    if (b < LERP_BLOCKS) {
        __shared__ float  sraw[64 * 17];            // staging: raw 64x16 tile
        __shared__ float4 tp2 [16 * TP2_STRIDE];    // pair table

        const int o      = b >> 3;
        const int c_base = (b & 7) * 64;
        const int lane   = t & 31;
        const int warp   = t >> 5;        // 0..7
        const int noq    = lane & 3;      // no quad
        const int c_idx  = lane >> 2;     // 0..7

        // --- stage raw tile (one coalesced float4 read per thread) ---
        {
            const float4 v = ((const float4*)(weight_H
                              + ((size_t)o * 512 + c_base) * 16))[t];
            const int r = t >> 2, q = (t & 3) * 4;
            float* d = sraw + r * 17 + q;
            d[0] = v.x; d[1] = v.y; d[2] = v.z; d[3] = v.w;
        }

        // --- per-thread (i0, frac): 2 ni x 4 no, registers only ---
        int   i0r[2][4];
        float frr[2][4];
        #pragma unroll
        for (int n2 = 0; n2 < 2; n2++) {
            const int ni = warp * 2 + n2;
            const float ih = __ldg(in_H + ni);
            #pragma unroll
            for (int j = 0; j < 4; j++) {
                const int no = noq * 4 + j;
                float d = ih - __ldg(out_H + no);
                float r = fmodf(d, TWO_PI_F);
                if (r < 0.0f) r += TWO_PI_F;
                float tt = r * (16.0f / TWO_PI_F);
                float fl = floorf(tt);
                i0r[n2][j] = ((int)fl) & 15;
                frr[n2][j] = tt - fl;
            }
        }
        __syncthreads();

        // --- build tp2: 512 entries, 2 per thread ---
        #pragma unroll
        for (int e = t; e < 512; e += 256) {
            const int k  = e >> 5;
            const int cc = e & 31;
            const int k1 = (k + 1) & 15;
            tp2[k * TP2_STRIDE + cc] = make_float4(
                sraw[cc * 17 + k],        sraw[cc * 17 + k1],
                sraw[(cc + 32) * 17 + k], sraw[(cc + 32) * 17 + k1]);
        }
        __syncthreads();

        // --- hot loop ---
        #pragma unroll
        for (int n2 = 0; n2 < 2; n2++) {
            const int ni = warp * 2 + n2;
            float* obase = out + ((((size_t)o * 16 + ni) * 512 + c_base) << 4)
                               + noq * 4;
            #pragma unroll 1
            for (int chunk = 0; chunk < 4; chunk++) {
                const int cc = chunk * 8 + c_idx;     // 0..31
                float rlo[4], rhi[4];
                #pragma unroll
                for (int j = 0; j < 4; j++) {
                    const float4 p = tp2[i0r[n2][j] * TP2_STRIDE + cc];
                    const float f = frr[n2][j];
                    rlo[j] = fmaf(f, p.y - p.x, p.x);
                    rhi[j] = fmaf(f, p.w - p.z, p.z);
                }
                __stcs((float4*)(obase + ((size_t)cc << 4)),
                       make_float4(rlo[0], rlo[1], rlo[2], rlo[3]));
                __stcs((float4*)(obase + ((size_t)(cc + 32) << 4)),
                       make_float4(rhi[0], rhi[1], rhi[2], rhi[3]));
            }
        }
        return;
    }

    // -------------------- rotated bilinear resample part --------------------
    const int idx = (b - LERP_BLOCKS) * 256 + t;
    if (idx >= ROT_TOTAL) return;

    const int pix = idx % (KS_DIM * KS_DIM);
    const int on  = idx / (KS_DIM * KS_DIM);
    const int no  = on & 15;
    const int o   = on >> 4;

    const float gx = grid_Rn[pix * 2 + 0];
    const float gy = grid_Rn[pix * 2 + 1];

    const float ang = -out_H[no];
    float sn, cs;
    sincosf(ang, &sn, &cs);
    const float xr = cs * gx - sn * gy;
    const float yr = sn * gx + cs * gy;

    const float x = (xr + 1.0f) * 0.5f * (float)(KS_DIM - 1);
    const float y = (yr + 1.0f) * 0.5f * (float)(KS_DIM - 1);
    const float x0f = floorf(x), y0f = floorf(y);
    const float wx = x - x0f,    wy = y - y0f;
    const int x0 = (int)x0f,     y0 = (int)y0f;

    const float* img = weight + o * (KS_DIM * KS_DIM);

    auto g = [&](int yy, int xx) -> float {
        if (yy < 0 || yy >= KS_DIM || xx < 0 || xx >= KS_DIM) return 0.0f;
        return img[yy * KS_DIM + xx];
    };

    const float v = (1.0f - wy) * (1.0f - wx) * g(y0,     x0)
                  + (1.0f - wy) * wx          * g(y0,     x0 + 1)
                  + wy          * (1.0f - wx) * g(y0 + 1, x0)
                  + wy          * wx          * g(y0 + 1, x0 + 1);

    out[OUT1_ELEMS + idx] = mask[pix] * v;
}

// ---------------------------------------------------------------------------
extern "C" void kernel_launch(void* const* d_in, const int* in_sizes, int n_in,
                              void* d_out, int out_size)
{
    const float* in_H     = (const float*)d_in[0];  // [16, 1]
    const float* out_H    = (const float*)d_in[1];  // [16, 1]
    const float* weight_H = (const float*)d_in[2];  // [512, 512, 16]
    const float* weight   = (const float*)d_in[3];  // [512, 1, 7, 7]
    // d_in[4] = grid_H (uniform grid, implicit; unused)
    const float* grid_Rn  = (const float*)d_in[5];  // [7, 7, 2]
    const float* mask     = (const float*)d_in[6];  // [7, 7]

    gsep_fused_kernel<<<LERP_BLOCKS + ROT_BLOCKS, 256>>>(
        in_H, out_H, weight_H, weight, grid_Rn, mask, (float*)d_out);
}